// round 1
// baseline (speedup 1.0000x reference)
#include <cuda_runtime.h>
#include <math.h>

#define B_SZ     128
#define L_Q      64
#define L_D      512
#define E_DIM    300
#define N_K      11
#define KT       50        // K-tile (300 = 6*50)
#define KSTEPS   6
#define NT       128       // d-tile per chunk
#define NCHUNKS  4         // 512/128
#define NTHREADS 256

__global__ __launch_bounds__(NTHREADS, 1)
void knrm_fused(const float* __restrict__ q,
                const float* __restrict__ d,
                const float* __restrict__ mq,
                const float* __restrict__ md,
                const float* __restrict__ w,
                const float* __restrict__ bias,
                float* __restrict__ out)
{
    __shared__ float As[L_Q][KT];       // [m][k]  (broadcast reads)
    __shared__ float Bs[KT][NT + 4];    // [k][n]  (+4 pad, conflict-free float4 reads)
    __shared__ float s_invq[L_Q];
    __shared__ float s_invd[L_D];
    __shared__ float s_maskd[L_D];
    __shared__ float s_pool[L_Q][N_K];
    __shared__ float s_red[L_Q];

    const int b    = blockIdx.x;
    const int tid  = threadIdx.x;
    const int lane = tid & 31;
    const int warp = tid >> 5;
    const int tx   = tid & 15;     // n-group (16)
    const int ty   = tid >> 4;     // m-group (16)
    const int m0   = ty * 4;
    const int nn0  = tx * 8;

    const float* __restrict__ qb = q + (size_t)b * L_Q * E_DIM;
    const float* __restrict__ db = d + (size_t)b * L_D * E_DIM;

    // ---- prologue: inverse L2 norms (warp per row) ----
    for (int r = warp; r < L_Q; r += 8) {
        float ss = 0.f;
        for (int k = lane; k < E_DIM; k += 32) { float v = qb[r * E_DIM + k]; ss = fmaf(v, v, ss); }
        #pragma unroll
        for (int o = 16; o > 0; o >>= 1) ss += __shfl_xor_sync(0xffffffffu, ss, o);
        if (lane == 0) s_invq[r] = 1.0f / fmaxf(sqrtf(ss), 1e-12f);
    }
    for (int r = warp; r < L_D; r += 8) {
        float ss = 0.f;
        for (int k = lane; k < E_DIM; k += 32) { float v = db[r * E_DIM + k]; ss = fmaf(v, v, ss); }
        #pragma unroll
        for (int o = 16; o > 0; o >>= 1) ss += __shfl_xor_sync(0xffffffffu, ss, o);
        if (lane == 0) s_invd[r] = 1.0f / fmaxf(sqrtf(ss), 1e-12f);
    }
    for (int i = tid; i < L_D; i += NTHREADS) s_maskd[i] = md[b * L_D + i];
    for (int i = tid; i < L_Q * N_K; i += NTHREADS) (&s_pool[0][0])[i] = 0.f;

    // RBF kernel constants (compile-time immediates after unroll)
    const float MU[N_K] = {1.0f, 0.9f, 0.7f, 0.5f, 0.3f, 0.1f,
                           -0.1f, -0.3f, -0.5f, -0.7f, -0.9f};
    const float CF[N_K] = {5.0e5f, 50.f, 50.f, 50.f, 50.f, 50.f,
                           50.f, 50.f, 50.f, 50.f, 50.f};   // 1/(2*sigma^2)

    float pool[4][N_K];
    #pragma unroll
    for (int i = 0; i < 4; ++i)
        #pragma unroll
        for (int k = 0; k < N_K; ++k) pool[i][k] = 0.f;

    for (int c = 0; c < NCHUNKS; ++c) {
        const int n0 = c * NT;
        float acc[4][8];
        #pragma unroll
        for (int i = 0; i < 4; ++i)
            #pragma unroll
            for (int j = 0; j < 8; ++j) acc[i][j] = 0.f;

        for (int ks = 0; ks < KSTEPS; ++ks) {
            const int k0 = ks * KT;
            __syncthreads();
            // A tile: 64x50, coalesced global runs of 50
            for (int idx = tid; idx < L_Q * KT; idx += NTHREADS) {
                int r = idx / KT, kc = idx - r * KT;
                As[r][kc] = qb[r * E_DIM + k0 + kc];
            }
            // B tile: 128x50, stored k-major (transposed)
            for (int idx = tid; idx < NT * KT; idx += NTHREADS) {
                int r = idx / KT, kc = idx - r * KT;
                Bs[kc][r] = db[(size_t)(n0 + r) * E_DIM + k0 + kc];
            }
            __syncthreads();

            #pragma unroll 2
            for (int kt = 0; kt < KT; kt += 2) {
                float2 a[4];
                #pragma unroll
                for (int i = 0; i < 4; ++i)
                    a[i] = *(const float2*)&As[m0 + i][kt];
                #pragma unroll
                for (int u = 0; u < 2; ++u) {
                    const float4 b0 = *(const float4*)&Bs[kt + u][nn0];
                    const float4 b1 = *(const float4*)&Bs[kt + u][nn0 + 4];
                    #pragma unroll
                    for (int i = 0; i < 4; ++i) {
                        const float av = u ? a[i].y : a[i].x;
                        acc[i][0] = fmaf(av, b0.x, acc[i][0]);
                        acc[i][1] = fmaf(av, b0.y, acc[i][1]);
                        acc[i][2] = fmaf(av, b0.z, acc[i][2]);
                        acc[i][3] = fmaf(av, b0.w, acc[i][3]);
                        acc[i][4] = fmaf(av, b1.x, acc[i][4]);
                        acc[i][5] = fmaf(av, b1.y, acc[i][5]);
                        acc[i][6] = fmaf(av, b1.z, acc[i][6]);
                        acc[i][7] = fmaf(av, b1.w, acc[i][7]);
                    }
                }
            }
        }

        // ---- fused RBF kernel pooling from accumulator registers ----
        float invd[8], mdv[8];
        #pragma unroll
        for (int j = 0; j < 8; ++j) {
            invd[j] = s_invd[n0 + nn0 + j];
            mdv[j]  = s_maskd[n0 + nn0 + j];
        }
        #pragma unroll
        for (int i = 0; i < 4; ++i) {
            const float iq = s_invq[m0 + i];
            #pragma unroll
            for (int j = 0; j < 8; ++j) {
                const float s = acc[i][j] * iq * invd[j];
                #pragma unroll
                for (int k = 0; k < N_K; ++k) {
                    const float t = s - MU[k];
                    pool[i][k] = fmaf(mdv[j], __expf(-(t * t) * CF[k]), pool[i][k]);
                }
            }
        }
    }

    // ---- reduce pooling partials across tx, then log/mask/dot/tanh ----
    __syncthreads();
    #pragma unroll
    for (int i = 0; i < 4; ++i)
        #pragma unroll
        for (int k = 0; k < N_K; ++k)
            atomicAdd(&s_pool[m0 + i][k], pool[i][k]);
    __syncthreads();

    if (tid < L_Q) {
        const float mqv = mq[b * L_Q + tid] * 0.01f;
        float cm = 0.f;
        #pragma unroll
        for (int k = 0; k < N_K; ++k) {
            const float ps = fmaxf(s_pool[tid][k], 1e-10f);
            cm = fmaf(logf(ps) * mqv, w[k], cm);
        }
        s_red[tid] = cm;
    }
    __syncthreads();
    if (tid == 0) {
        float s = bias[0];
        for (int m = 0; m < L_Q; ++m) s += s_red[m];
        out[b] = tanhf(s);
    }
}

extern "C" void kernel_launch(void* const* d_in, const int* in_sizes, int n_in,
                              void* d_out, int out_size) {
    const float* q    = (const float*)d_in[0];   // [B, Lq, E]
    const float* d    = (const float*)d_in[1];   // [B, Ld, E]
    const float* mq   = (const float*)d_in[2];   // [B, Lq]
    const float* md   = (const float*)d_in[3];   // [B, Ld]
    const float* w    = (const float*)d_in[4];   // [1, K]
    const float* bias = (const float*)d_in[5];   // [1]
    float* out = (float*)d_out;                  // [B, 1]

    knrm_fused<<<B_SZ, NTHREADS>>>(q, d, mq, md, w, bias, out);
}